// round 16
// baseline (speedup 1.0000x reference)
#include <cuda_runtime.h>
#include <math.h>
#include <stdint.h>

#define NB   8
#define NN   256
#define NH   4
#define HD   64
#define FIN  256
#define ALPHA 0.2f

// ---------------- scratch (__device__ globals; no allocs allowed) ----------
__device__ float g_Wh [NB*NH*NN*HD];
__device__ float g_si2[NB*NH*NN*HD];
__device__ float g_sj2[NB*NH*NN*HD];
__device__ float g_ei [NB*NH*NN*HD];
__device__ float g_ej [NB*NH*NN*HD];
__device__ float g_concat[NB*NN*FIN];
__device__ float g_out2[NB*NN*FIN];    // pre-LN output of k3a

// ---------------- packed helpers -------------------------------------------
__device__ __forceinline__ uint32_t packbf(float lo, float hi) {
    uint32_t r;
    asm("cvt.rn.bf16x2.f32 %0, %1, %2;" : "=r"(r) : "f"(hi), "f"(lo));
    return r;
}
__device__ __forceinline__ uint32_t hadd2(uint32_t a, uint32_t b) {
    uint32_t r;
    asm("add.rn.bf16x2 %0, %1, %2;" : "=r"(r) : "r"(a), "r"(b));
    return r;
}
__device__ __forceinline__ uint32_t habs2(uint32_t a) { return a & 0x7FFF7FFFu; }

__device__ __forceinline__ void mma16816(float* c, uint32_t a0, uint32_t a1,
                                         uint32_t a2, uint32_t a3,
                                         uint32_t b0, uint32_t b1) {
    asm volatile("mma.sync.aligned.m16n8k16.row.col.f32.bf16.bf16.f32 "
                 "{%0,%1,%2,%3}, {%4,%5,%6,%7}, {%8,%9}, {%0,%1,%2,%3};"
                 : "+f"(c[0]), "+f"(c[1]), "+f"(c[2]), "+f"(c[3])
                 : "r"(a0), "r"(a1), "r"(a2), "r"(a3), "r"(b0), "r"(b1));
}
__device__ __forceinline__ uint32_t cvt_tf32(float x) {
    uint32_t r; asm("cvt.rna.tf32.f32 %0, %1;" : "=r"(r) : "f"(x)); return r;
}
__device__ __forceinline__ float cvt_tf32f(float x) {
    return __uint_as_float(cvt_tf32(x));
}
__device__ __forceinline__ void mma1688(float* c, uint32_t a0, uint32_t a1,
                                        uint32_t a2, uint32_t a3,
                                        uint32_t b0, uint32_t b1) {
    asm volatile("mma.sync.aligned.m16n8k8.row.col.f32.tf32.tf32.f32 "
                 "{%0,%1,%2,%3}, {%4,%5,%6,%7}, {%8,%9}, {%0,%1,%2,%3};"
                 : "+f"(c[0]), "+f"(c[1]), "+f"(c[2]), "+f"(c[3])
                 : "r"(a0), "r"(a1), "r"(a2), "r"(a3), "r"(b0), "r"(b1));
}

// ---------------------------------------------------------------------------
// k1a (tf32): phase A only, column-halved (unchanged from R15).
// ---------------------------------------------------------------------------
#define K1A_BYTES (256*24*4)

__global__ __launch_bounds__(256) void k1a(
    const float* __restrict__ hin, const float* __restrict__ W,
    const float* __restrict__ We1, const float* __restrict__ be1)
{
    extern __shared__ __align__(16) float s1[];
    int bx = blockIdx.x;
    int b  = bx >> 5;
    int nt4 = (bx >> 1) & 15;
    int ch = bx & 1;
    int n0 = nt4 * 16;
    int tid = threadIdx.x;
    int wid = tid >> 5, lane = tid & 31;
    int gid = lane >> 2, tig = lane & 3;

    {
        const float* hrow = hin + ((size_t)b*NN + n0)*FIN + tid;
#pragma unroll
        for (int r = 0; r < 16; ++r)
            s1[tid*24 + r] = cvt_tf32f(hrow[(size_t)r*FIN]);
    }
    __syncthreads();

    const float* wp[6];
#pragma unroll
    for (int nt = 0; nt < 6; ++nt) {
        int ntg = ch*48 + wid*6 + nt;
        int mat = ntg >> 5, rem = ntg & 31;
        int head = rem >> 3, d0 = (rem & 7)*8;
        const float* base = (mat == 0)
            ? (W + (size_t)head*FIN*HD)
            : (We1 + (size_t)head*2*FIN*HD + (size_t)(mat-1)*FIN*HD);
        wp[nt] = base + d0 + gid;
    }

    float acc[6][4];
#pragma unroll
    for (int nt = 0; nt < 6; ++nt)
        acc[nt][0]=acc[nt][1]=acc[nt][2]=acc[nt][3]=0.f;

#pragma unroll 2
    for (int k0 = 0; k0 < FIN; k0 += 8) {
        uint32_t a0 = __float_as_uint(s1[(k0+tig)*24 + gid]);
        uint32_t a1 = __float_as_uint(s1[(k0+tig)*24 + gid + 8]);
        uint32_t a2 = __float_as_uint(s1[(k0+tig+4)*24 + gid]);
        uint32_t a3 = __float_as_uint(s1[(k0+tig+4)*24 + gid + 8]);
        int off0 = (k0+tig)*HD, off1 = (k0+tig+4)*HD;
#pragma unroll
        for (int nt = 0; nt < 6; ++nt) {
            uint32_t b0 = cvt_tf32(wp[nt][off0]);
            uint32_t b1 = cvt_tf32(wp[nt][off1]);
            mma1688(acc[nt], a0, a1, a2, a3, b0, b1);
        }
    }

#pragma unroll
    for (int nt = 0; nt < 6; ++nt) {
        int ntg = ch*48 + wid*6 + nt;
        int mat = ntg >> 5, rem = ntg & 31;
        int head = rem >> 3, d0 = (rem & 7)*8;
        int c0 = d0 + 2*tig;
        float v00 = acc[nt][0], v01 = acc[nt][1], v10 = acc[nt][2], v11 = acc[nt][3];
        if (mat == 1) {
            float e0 = be1[head*HD + c0], e1 = be1[head*HD + c0 + 1];
            v00 += e0; v01 += e1; v10 += e0; v11 += e1;
        }
        float* gout = (mat == 0) ? g_Wh : ((mat == 1) ? g_ei : g_ej);
        size_t rbase = ((size_t)(b*NH + head)*NN + n0);
        *reinterpret_cast<float2*>(&gout[(rbase + gid)*HD + c0])     = make_float2(v00, v01);
        *reinterpret_cast<float2*>(&gout[(rbase + gid + 8)*HD + c0]) = make_float2(v10, v11);
    }
}

// ---------------------------------------------------------------------------
// k1b2 (tf32): si2/sj2 concat GEMM (unchanged from R15).
// ---------------------------------------------------------------------------
#define K1B_BYTES (8*64*24*4)

__global__ __launch_bounds__(256) void k1b2(
    const float* __restrict__ Wa1, const float* __restrict__ ba1)
{
    extern __shared__ __align__(16) float s1[];
    int bx = blockIdx.x;
    int which = bx & 1;
    int nt16  = (bx >> 1) & 15;
    int b     = bx >> 5;
    int n0 = nt16 * 16;
    int tid = threadIdx.x;
    int wid = tid >> 5, lane = tid & 31;
    int gid = lane >> 2, tig = lane & 3;

    const float* hi_src = which ? g_ej : g_ei;

    for (int idx = tid; idx < 8192; idx += 256) {
        int tile = idx >> 10;
        int head = tile >> 1, part = tile & 1;
        int r = (idx >> 6) & 15, d = idx & 63;
        const float* src = part ? hi_src : g_Wh;
        float v = src[((size_t)(b*NH + head)*NN + n0 + r)*HD + d];
        s1[tile*1536 + d*24 + r] = cvt_tf32f(v);
    }
    __syncthreads();

    int head = wid >> 1, chal = wid & 1;
    int tlo = (head*2    )*1536;
    int thi = (head*2 + 1)*1536;
    const float* Blo = Wa1 + ((size_t)head*3*HD + which*HD)*HD;
    const float* Bhi = Wa1 + ((size_t)head*3*HD + 2*HD)*HD;

    float acc[4][4];
#pragma unroll
    for (int nt = 0; nt < 4; ++nt)
        acc[nt][0]=acc[nt][1]=acc[nt][2]=acc[nt][3]=0.f;

#pragma unroll 2
    for (int ks = 0; ks < 8; ++ks) {
        int k0 = ks*8;
        uint32_t a0 = __float_as_uint(s1[tlo + (k0+tig)*24 + gid]);
        uint32_t a1 = __float_as_uint(s1[tlo + (k0+tig)*24 + gid + 8]);
        uint32_t a2 = __float_as_uint(s1[tlo + (k0+tig+4)*24 + gid]);
        uint32_t a3 = __float_as_uint(s1[tlo + (k0+tig+4)*24 + gid + 8]);
#pragma unroll
        for (int nt = 0; nt < 4; ++nt) {
            int col = chal*32 + nt*8 + gid;
            uint32_t b0 = cvt_tf32(Blo[(k0+tig)*HD + col]);
            uint32_t b1 = cvt_tf32(Blo[(k0+tig+4)*HD + col]);
            mma1688(acc[nt], a0, a1, a2, a3, b0, b1);
        }
    }
#pragma unroll 2
    for (int ks = 0; ks < 8; ++ks) {
        int k0 = ks*8;
        uint32_t a0 = __float_as_uint(s1[thi + (k0+tig)*24 + gid]);
        uint32_t a1 = __float_as_uint(s1[thi + (k0+tig)*24 + gid + 8]);
        uint32_t a2 = __float_as_uint(s1[thi + (k0+tig+4)*24 + gid]);
        uint32_t a3 = __float_as_uint(s1[thi + (k0+tig+4)*24 + gid + 8]);
#pragma unroll
        for (int nt = 0; nt < 4; ++nt) {
            int col = chal*32 + nt*8 + gid;
            uint32_t b0 = cvt_tf32(0.6f * Bhi[(k0+tig)*HD + col]);
            uint32_t b1 = cvt_tf32(0.6f * Bhi[(k0+tig+4)*HD + col]);
            mma1688(acc[nt], a0, a1, a2, a3, b0, b1);
        }
    }

    float* gout = which ? g_sj2 : g_si2;
#pragma unroll
    for (int nt = 0; nt < 4; ++nt) {
        int c0 = chal*32 + nt*8 + 2*tig;
        float v00=acc[nt][0], v01=acc[nt][1], v10=acc[nt][2], v11=acc[nt][3];
        if (which == 0) {
            float b0v = ba1[head*HD + c0], b1v = ba1[head*HD + c0 + 1];
            v00 += b0v; v01 += b1v; v10 += b0v; v11 += b1v;
        }
        size_t rbase = ((size_t)(b*NH + head)*NN + n0);
        *reinterpret_cast<float2*>(&gout[(rbase + gid)*HD + c0])     = make_float2(v00, v01);
        *reinterpret_cast<float2*>(&gout[(rbase + gid + 8)*HD + c0]) = make_float2(v10, v11);
    }
}

// ---------------------------------------------------------------------------
// t2f: exact R13/R15 (unchanged).
// ---------------------------------------------------------------------------
#define O_EJ    0
#define O_WEBF  9216
#define O_EI    11264
#define O_SI    11776
#define O_WA2   12800
#define O_ET    12864
#define O_HP    17472
#define T2_FLOATS 18560
#define T2_BYTES  (T2_FLOATS*4)

__global__ __launch_bounds__(256, 2) void t2f(
    const float* __restrict__ Wa1, const float* __restrict__ wa2,
    const int*   __restrict__ adj, const float* __restrict__ ba2,
    const float* __restrict__ ln_g, const float* __restrict__ ln_b)
{
    extern __shared__ __align__(16) float sm[];
    uint32_t* smu = reinterpret_cast<uint32_t*>(sm);

    int bx   = blockIdx.x;
    int it   = bx & 15;
    int head = (bx >> 4) & 3;
    int b    = bx >> 6;
    int i0   = it * 16;
    int tid  = threadIdx.x;
    int wid  = tid >> 5, lane = tid & 31;
    int gid  = lane >> 2, tig = lane & 3;

    size_t bh = (size_t)(b*NH + head);
    const float* sj_base = g_sj2 + bh*NN*HD;
    const float* wh_base = g_Wh  + bh*NN*HD;

    for (int t = tid; t < NN*32; t += 256) {
        int j = t >> 5, kk = t & 31;
        float2 v = *reinterpret_cast<const float2*>(&g_ej[(bh*NN + j)*HD + 2*kk]);
        smu[O_EJ + j*36 + kk] = packbf(v.x, v.y);
    }
    for (int t = tid; t < 2048; t += 256) {
        int c   = t & 1;
        int ln2 = (t >> 1) & 31;
        int q   = t >> 6;
        int ks  = q >> 3, nt = q & 7;
        int tg  = ln2 & 3, gd = ln2 >> 2;
        int kk  = ks*8 + tg + (c ? 4 : 0);
        int d   = nt*8 + gd;
        float f0 = 0.4f * Wa1[((size_t)head*3*HD + 2*HD + 2*kk    )*HD + d];
        float f1 = 0.4f * Wa1[((size_t)head*3*HD + 2*HD + 2*kk + 1)*HD + d];
        smu[O_WEBF + t] = packbf(f0, f1);
    }
    for (int t = tid; t < 16*32; t += 256) {
        int ii = t >> 5, kk = t & 31;
        float2 v = *reinterpret_cast<const float2*>(&g_ei[(bh*NN + i0 + ii)*HD + 2*kk]);
        smu[O_EI + t] = packbf(v.x, v.y);
    }
    for (int t = tid; t < 16*64; t += 256) {
        int ii = t >> 6, d = t & 63;
        sm[O_SI + t] = g_si2[(bh*NN + i0 + ii)*HD + d];
    }
    if (tid < 64) sm[O_WA2 + tid] = wa2[head*HD + tid];
    __syncthreads();

    unsigned long long bfr[4][8];
#pragma unroll
    for (int ks = 0; ks < 4; ++ks)
#pragma unroll
        for (int nt = 0; nt < 8; ++nt)
            bfr[ks][nt] = *reinterpret_cast<const unsigned long long*>(
                &smu[O_WEBF + ((ks*8 + nt)*32 + lane)*2]);

    for (int ii = 0; ii < 16; ++ii) {
        uint32_t eir[8];
#pragma unroll
        for (int ks = 0; ks < 4; ++ks) {
            eir[2*ks]   = smu[O_EI + ii*32 + ks*8 + tig];
            eir[2*ks+1] = smu[O_EI + ii*32 + ks*8 + 4 + tig];
        }
#pragma unroll
        for (int p = 0; p < 2; ++p) {
            int j0 = (wid + 8*p) * 16;
            int r0 = j0 + gid, r1 = r0 + 8;

            float acc[8][4];
#pragma unroll
            for (int nt = 0; nt < 8; ++nt) {
                float2 s = *reinterpret_cast<const float2*>(&sm[O_SI + ii*64 + nt*8 + 2*tig]);
                acc[nt][0] = s.x; acc[nt][1] = s.y; acc[nt][2] = s.x; acc[nt][3] = s.y;
            }
#pragma unroll
            for (int ks = 0; ks < 4; ++ks) {
                uint32_t a0 = habs2(hadd2(smu[O_EJ + r0*36 + ks*8 + tig],     eir[2*ks]));
                uint32_t a1 = habs2(hadd2(smu[O_EJ + r1*36 + ks*8 + tig],     eir[2*ks]));
                uint32_t a2 = habs2(hadd2(smu[O_EJ + r0*36 + ks*8 + 4 + tig], eir[2*ks+1]));
                uint32_t a3 = habs2(hadd2(smu[O_EJ + r1*36 + ks*8 + 4 + tig], eir[2*ks+1]));
#pragma unroll
                for (int nt = 0; nt < 8; ++nt) {
                    uint32_t b0 = (uint32_t)(bfr[ks][nt] & 0xffffffffu);
                    uint32_t b1 = (uint32_t)(bfr[ks][nt] >> 32);
                    mma16816(acc[nt], a0, a1, a2, a3, b0, b1);
                }
            }
            float pe0 = 0.f, pe1 = 0.f;
#pragma unroll
            for (int nt = 0; nt < 8; ++nt) {
                int d = nt*8 + 2*tig;
                float2 sj0 = *reinterpret_cast<const float2*>(&sj_base[(size_t)r0*HD + d]);
                float2 sj1 = *reinterpret_cast<const float2*>(&sj_base[(size_t)r1*HD + d]);
                float2 w2  = *reinterpret_cast<const float2*>(&sm[O_WA2 + d]);
                float v00 = acc[nt][0] + sj0.x, v01 = acc[nt][1] + sj0.y;
                float v10 = acc[nt][2] + sj1.x, v11 = acc[nt][3] + sj1.y;
                pe0 = fmaf(fmaxf(v00, ALPHA*v00), w2.x, pe0);
                pe0 = fmaf(fmaxf(v01, ALPHA*v01), w2.y, pe0);
                pe1 = fmaf(fmaxf(v10, ALPHA*v10), w2.x, pe1);
                pe1 = fmaf(fmaxf(v11, ALPHA*v11), w2.y, pe1);
            }
            pe0 += __shfl_xor_sync(0xffffffffu, pe0, 1);
            pe0 += __shfl_xor_sync(0xffffffffu, pe0, 2);
            pe1 += __shfl_xor_sync(0xffffffffu, pe1, 1);
            pe1 += __shfl_xor_sync(0xffffffffu, pe1, 2);
            if (tig == 0) {
                sm[O_ET + r0*18 + ii] = pe0;
                sm[O_ET + r1*18 + ii] = pe1;
            }
        }
    }
    __syncthreads();

    {
        float bav = ba2[head];
#pragma unroll
        for (int r = 0; r < 2; ++r) {
            int i = wid*2 + r;
            int iglob = i0 + i;
            float vals[8]; float mx = -1e30f;
#pragma unroll
            for (int s = 0; s < 8; ++s) {
                int j = lane + 32*s;
                float pe = sm[O_ET + j*18 + i] + bav;
                int a = adj[((size_t)b*NN + iglob)*NN + j];
                vals[s] = (a == 0) ? -1e9f : pe;
                mx = fmaxf(mx, vals[s]);
            }
#pragma unroll
            for (int o = 16; o; o >>= 1) mx = fmaxf(mx, __shfl_xor_sync(0xffffffffu, mx, o));
            float se = 0.f;
#pragma unroll
            for (int s = 0; s < 8; ++s) { vals[s] = __expf(vals[s] - mx); se += vals[s]; }
#pragma unroll
            for (int o = 16; o; o >>= 1) se += __shfl_xor_sync(0xffffffffu, se, o);
            float inv = 1.0f / se;
#pragma unroll
            for (int s = 0; s < 8; ++s)
                sm[O_ET + (lane + 32*s)*18 + i] = vals[s] * inv;
        }
    }
    __syncthreads();

    {
        int n0w = wid * 8;
        float hacc[4] = {0.f, 0.f, 0.f, 0.f};
#pragma unroll 4
        for (int ks = 0; ks < 32; ++ks) {
            int k0 = ks*8;
            uint32_t a0 = cvt_tf32(sm[O_ET + (k0+tig)*18 + gid]);
            uint32_t a1 = cvt_tf32(sm[O_ET + (k0+tig)*18 + gid + 8]);
            uint32_t a2 = cvt_tf32(sm[O_ET + (k0+tig+4)*18 + gid]);
            uint32_t a3 = cvt_tf32(sm[O_ET + (k0+tig+4)*18 + gid + 8]);
            uint32_t b0 = cvt_tf32(wh_base[(size_t)(k0+tig)*HD + n0w + gid]);
            uint32_t b1 = cvt_tf32(wh_base[(size_t)(k0+tig+4)*HD + n0w + gid]);
            mma1688(hacc, a0, a1, a2, a3, b0, b1);
        }
        int c0 = n0w + 2*tig;
        sm[O_HP + gid*68 + c0]         = hacc[0];
        sm[O_HP + gid*68 + c0 + 1]     = hacc[1];
        sm[O_HP + (gid+8)*68 + c0]     = hacc[2];
        sm[O_HP + (gid+8)*68 + c0 + 1] = hacc[3];
    }
    __syncthreads();

    {
#pragma unroll
        for (int r = 0; r < 2; ++r) {
            int i = wid*2 + r;
            float x0 = sm[O_HP + i*68 + lane];
            float x1 = sm[O_HP + i*68 + 32 + lane];
            float s1v = x0 + x1, s2v = x0*x0 + x1*x1;
#pragma unroll
            for (int o = 16; o; o >>= 1) {
                s1v += __shfl_xor_sync(0xffffffffu, s1v, o);
                s2v += __shfl_xor_sync(0xffffffffu, s2v, o);
            }
            float m   = s1v * (1.0f/64.0f);
            float var = s2v * (1.0f/64.0f) - m*m;
            float rr  = rsqrtf(var + 1e-5f);
            size_t obase = ((size_t)(b*NN) + i0 + i)*FIN + head*HD;
            g_concat[obase + lane]      = (x0 - m)*rr*ln_g[head*HD + lane]      + ln_b[head*HD + lane];
            g_concat[obase + 32 + lane] = (x1 - m)*rr*ln_g[head*HD + 32 + lane] + ln_b[head*HD + 32 + lane];
        }
    }
}

// ---------------------------------------------------------------------------
// k3a (tf32 MMA): col-split output GEMM. Block = (b, 16-row tile, col-half).
// grid 256. Writes concat@Wo + bo + h (pre-LN) to g_out2.
// ---------------------------------------------------------------------------
__global__ __launch_bounds__(256) void k3a(
    const float* __restrict__ hin, const float* __restrict__ Wo,
    const float* __restrict__ bo)
{
    __shared__ __align__(16) float cst[FIN*24];
    int bx = blockIdx.x;
    int ch = bx & 1;
    int nt16 = (bx >> 1) & 15;
    int b  = bx >> 5;
    int n0 = nt16 * 16;
    int tid = threadIdx.x;
    int wid = tid >> 5, lane = tid & 31;
    int gid = lane >> 2, tig = lane & 3;

    {
        const float* crow = g_concat + ((size_t)b*NN + n0)*FIN + tid;
#pragma unroll
        for (int r = 0; r < 16; ++r)
            cst[tid*24 + r] = cvt_tf32f(crow[(size_t)r*FIN]);
    }
    __syncthreads();

    float acc[2][4];
#pragma unroll
    for (int nt = 0; nt < 2; ++nt)
        acc[nt][0]=acc[nt][1]=acc[nt][2]=acc[nt][3]=0.f;

#pragma unroll 2
    for (int k0 = 0; k0 < FIN; k0 += 8) {
        uint32_t a0 = __float_as_uint(cst[(k0+tig)*24 + gid]);
        uint32_t a1 = __float_as_uint(cst[(k0+tig)*24 + gid + 8]);
        uint32_t a2 = __float_as_uint(cst[(k0+tig+4)*24 + gid]);
        uint32_t a3 = __float_as_uint(cst[(k0+tig+4)*24 + gid + 8]);
#pragma unroll
        for (int nt = 0; nt < 2; ++nt) {
            int col = ch*128 + wid*16 + nt*8 + gid;
            uint32_t b0 = cvt_tf32(Wo[(size_t)(k0+tig)*FIN + col]);
            uint32_t b1 = cvt_tf32(Wo[(size_t)(k0+tig+4)*FIN + col]);
            mma1688(acc[nt], a0, a1, a2, a3, b0, b1);
        }
    }

#pragma unroll
    for (int nt = 0; nt < 2; ++nt) {
        int c0 = ch*128 + wid*16 + nt*8 + 2*tig;
        float b0v = bo[c0], b1v = bo[c0+1];
        float2 h0 = *reinterpret_cast<const float2*>(&hin[((size_t)b*NN + n0 + gid)*FIN + c0]);
        float2 h1 = *reinterpret_cast<const float2*>(&hin[((size_t)b*NN + n0 + gid + 8)*FIN + c0]);
        *reinterpret_cast<float2*>(&g_out2[((size_t)b*NN + n0 + gid)*FIN + c0]) =
            make_float2(acc[nt][0] + b0v + h0.x, acc[nt][1] + b1v + h0.y);
        *reinterpret_cast<float2*>(&g_out2[((size_t)b*NN + n0 + gid + 8)*FIN + c0]) =
            make_float2(acc[nt][2] + b0v + h1.x, acc[nt][3] + b1v + h1.y);
    }
}

// ---------------------------------------------------------------------------
// k3b: layernorm only. Block = (b, 8 rows), grid 256; warp per row.
// ---------------------------------------------------------------------------
__global__ __launch_bounds__(256) void k3b(
    const float* __restrict__ g2, const float* __restrict__ b2,
    float* __restrict__ out)
{
    int b  = blockIdx.x >> 5;
    int n0 = (blockIdx.x & 31) * 8;
    int tid = threadIdx.x;
    int wid = tid >> 5, lane = tid & 31;

    const float* row = g_out2 + ((size_t)b*NN + n0 + wid)*FIN;
    float x[8];
    float s1v = 0.f, s2v = 0.f;
#pragma unroll
    for (int k = 0; k < 8; ++k) {
        x[k] = row[k*32 + lane];
        s1v += x[k]; s2v += x[k]*x[k];
    }
#pragma unroll
    for (int o = 16; o; o >>= 1) {
        s1v += __shfl_xor_sync(0xffffffffu, s1v, o);
        s2v += __shfl_xor_sync(0xffffffffu, s2v, o);
    }
    float m   = s1v * (1.0f/256.0f);
    float var = s2v * (1.0f/256.0f) - m*m;
    float rr  = rsqrtf(var + 1e-5f);
    float* orow = out + ((size_t)b*NN + n0 + wid)*FIN;
#pragma unroll
    for (int k = 0; k < 8; ++k) {
        int c = k*32 + lane;
        orow[c] = (x[k] - m)*rr*g2[c] + b2[c];
    }
}

// ---------------------------------------------------------------------------
extern "C" void kernel_launch(void* const* d_in, const int* in_sizes, int n_in,
                              void* d_out, int out_size)
{
    const float* h    = (const float*)d_in[0];
    const int*   adj  = (const int*)  d_in[1];
    const float* W    = (const float*)d_in[2];
    const float* We1  = (const float*)d_in[3];
    const float* be1  = (const float*)d_in[4];
    const float* Wa1  = (const float*)d_in[5];
    const float* ba1  = (const float*)d_in[6];
    const float* wa2  = (const float*)d_in[7];
    const float* ba2  = (const float*)d_in[8];
    const float* ln_g = (const float*)d_in[9];
    const float* ln_b = (const float*)d_in[10];
    const float* Wo   = (const float*)d_in[11];
    const float* bo   = (const float*)d_in[12];
    const float* g2   = (const float*)d_in[13];
    const float* b2   = (const float*)d_in[14];
    float* out = (float*)d_out;

    cudaFuncSetAttribute(k1a,  cudaFuncAttributeMaxDynamicSharedMemorySize, K1A_BYTES);
    cudaFuncSetAttribute(k1b2, cudaFuncAttributeMaxDynamicSharedMemorySize, K1B_BYTES);
    cudaFuncSetAttribute(t2f,  cudaFuncAttributeMaxDynamicSharedMemorySize, T2_BYTES);

    k1a  <<<NB*16*2, 256, K1A_BYTES>>>(h, W, We1, be1);
    k1b2 <<<NB*16*2, 256, K1B_BYTES>>>(Wa1, ba1);
    t2f  <<<NB*NH*(NN/16), 256, T2_BYTES>>>(Wa1, wa2, adj, ba2, ln_g, ln_b);
    k3a  <<<NB*16*2, 256>>>(h, Wo, bo);
    k3b  <<<NB*(NN/8), 256>>>(g2, b2, out);
}

// round 17
// speedup vs baseline: 1.0074x; 1.0074x over previous
#include <cuda_runtime.h>
#include <math.h>
#include <stdint.h>

#define NB   8
#define NN   256
#define NH   4
#define HD   64
#define FIN  256
#define ALPHA 0.2f

// ---------------- scratch (__device__ globals; no allocs allowed) ----------
__device__ float g_Wh [NB*NH*NN*HD];
__device__ float g_si2[NB*NH*NN*HD];
__device__ float g_sj2[NB*NH*NN*HD];
__device__ float g_ei [NB*NH*NN*HD];
__device__ float g_ej [NB*NH*NN*HD];
__device__ float g_concat[NB*NN*FIN];

// ---------------- packed helpers -------------------------------------------
__device__ __forceinline__ uint32_t packbf(float lo, float hi) {
    uint32_t r;
    asm("cvt.rn.bf16x2.f32 %0, %1, %2;" : "=r"(r) : "f"(hi), "f"(lo));
    return r;
}
__device__ __forceinline__ uint32_t hadd2(uint32_t a, uint32_t b) {
    uint32_t r;
    asm("add.rn.bf16x2 %0, %1, %2;" : "=r"(r) : "r"(a), "r"(b));
    return r;
}
__device__ __forceinline__ uint32_t habs2(uint32_t a) { return a & 0x7FFF7FFFu; }

__device__ __forceinline__ void mma16816(float* c, uint32_t a0, uint32_t a1,
                                         uint32_t a2, uint32_t a3,
                                         uint32_t b0, uint32_t b1) {
    asm volatile("mma.sync.aligned.m16n8k16.row.col.f32.bf16.bf16.f32 "
                 "{%0,%1,%2,%3}, {%4,%5,%6,%7}, {%8,%9}, {%0,%1,%2,%3};"
                 : "+f"(c[0]), "+f"(c[1]), "+f"(c[2]), "+f"(c[3])
                 : "r"(a0), "r"(a1), "r"(a2), "r"(a3), "r"(b0), "r"(b1));
}
__device__ __forceinline__ uint32_t cvt_tf32(float x) {
    uint32_t r; asm("cvt.rna.tf32.f32 %0, %1;" : "=r"(r) : "f"(x)); return r;
}
__device__ __forceinline__ float cvt_tf32f(float x) {
    return __uint_as_float(cvt_tf32(x));
}
__device__ __forceinline__ void mma1688(float* c, uint32_t a0, uint32_t a1,
                                        uint32_t a2, uint32_t a3,
                                        uint32_t b0, uint32_t b1) {
    asm volatile("mma.sync.aligned.m16n8k8.row.col.f32.tf32.tf32.f32 "
                 "{%0,%1,%2,%3}, {%4,%5,%6,%7}, {%8,%9}, {%0,%1,%2,%3};"
                 : "+f"(c[0]), "+f"(c[1]), "+f"(c[2]), "+f"(c[3])
                 : "r"(a0), "r"(a1), "r"(a2), "r"(a3), "r"(b0), "r"(b1));
}

// ---------------------------------------------------------------------------
// k1a (tf32): phase A only, column-halved. Deeper unroll for MLP.
// ---------------------------------------------------------------------------
#define K1A_BYTES (256*24*4)

__global__ __launch_bounds__(256) void k1a(
    const float* __restrict__ hin, const float* __restrict__ W,
    const float* __restrict__ We1, const float* __restrict__ be1)
{
    extern __shared__ __align__(16) float s1[];
    int bx = blockIdx.x;
    int b  = bx >> 5;
    int nt4 = (bx >> 1) & 15;
    int ch = bx & 1;
    int n0 = nt4 * 16;
    int tid = threadIdx.x;
    int wid = tid >> 5, lane = tid & 31;
    int gid = lane >> 2, tig = lane & 3;

    {
        const float* hrow = hin + ((size_t)b*NN + n0)*FIN + tid;
#pragma unroll
        for (int r = 0; r < 16; ++r)
            s1[tid*24 + r] = cvt_tf32f(hrow[(size_t)r*FIN]);
    }
    __syncthreads();

    const float* wp[6];
#pragma unroll
    for (int nt = 0; nt < 6; ++nt) {
        int ntg = ch*48 + wid*6 + nt;
        int mat = ntg >> 5, rem = ntg & 31;
        int head = rem >> 3, d0 = (rem & 7)*8;
        const float* base = (mat == 0)
            ? (W + (size_t)head*FIN*HD)
            : (We1 + (size_t)head*2*FIN*HD + (size_t)(mat-1)*FIN*HD);
        wp[nt] = base + d0 + gid;
    }

    float acc[6][4];
#pragma unroll
    for (int nt = 0; nt < 6; ++nt)
        acc[nt][0]=acc[nt][1]=acc[nt][2]=acc[nt][3]=0.f;

#pragma unroll 4
    for (int k0 = 0; k0 < FIN; k0 += 8) {
        uint32_t a0 = __float_as_uint(s1[(k0+tig)*24 + gid]);
        uint32_t a1 = __float_as_uint(s1[(k0+tig)*24 + gid + 8]);
        uint32_t a2 = __float_as_uint(s1[(k0+tig+4)*24 + gid]);
        uint32_t a3 = __float_as_uint(s1[(k0+tig+4)*24 + gid + 8]);
        int off0 = (k0+tig)*HD, off1 = (k0+tig+4)*HD;
#pragma unroll
        for (int nt = 0; nt < 6; ++nt) {
            uint32_t b0 = cvt_tf32(wp[nt][off0]);
            uint32_t b1 = cvt_tf32(wp[nt][off1]);
            mma1688(acc[nt], a0, a1, a2, a3, b0, b1);
        }
    }

#pragma unroll
    for (int nt = 0; nt < 6; ++nt) {
        int ntg = ch*48 + wid*6 + nt;
        int mat = ntg >> 5, rem = ntg & 31;
        int head = rem >> 3, d0 = (rem & 7)*8;
        int c0 = d0 + 2*tig;
        float v00 = acc[nt][0], v01 = acc[nt][1], v10 = acc[nt][2], v11 = acc[nt][3];
        if (mat == 1) {
            float e0 = be1[head*HD + c0], e1 = be1[head*HD + c0 + 1];
            v00 += e0; v01 += e1; v10 += e0; v11 += e1;
        }
        float* gout = (mat == 0) ? g_Wh : ((mat == 1) ? g_ei : g_ej);
        size_t rbase = ((size_t)(b*NH + head)*NN + n0);
        *reinterpret_cast<float2*>(&gout[(rbase + gid)*HD + c0])     = make_float2(v00, v01);
        *reinterpret_cast<float2*>(&gout[(rbase + gid + 8)*HD + c0]) = make_float2(v10, v11);
    }
}

// ---------------------------------------------------------------------------
// k1b2 (tf32): si2/sj2 concat GEMM. Deeper unroll for MLP.
// ---------------------------------------------------------------------------
#define K1B_BYTES (8*64*24*4)

__global__ __launch_bounds__(256) void k1b2(
    const float* __restrict__ Wa1, const float* __restrict__ ba1)
{
    extern __shared__ __align__(16) float s1[];
    int bx = blockIdx.x;
    int which = bx & 1;
    int nt16  = (bx >> 1) & 15;
    int b     = bx >> 5;
    int n0 = nt16 * 16;
    int tid = threadIdx.x;
    int wid = tid >> 5, lane = tid & 31;
    int gid = lane >> 2, tig = lane & 3;

    const float* hi_src = which ? g_ej : g_ei;

    for (int idx = tid; idx < 8192; idx += 256) {
        int tile = idx >> 10;
        int head = tile >> 1, part = tile & 1;
        int r = (idx >> 6) & 15, d = idx & 63;
        const float* src = part ? hi_src : g_Wh;
        float v = src[((size_t)(b*NH + head)*NN + n0 + r)*HD + d];
        s1[tile*1536 + d*24 + r] = cvt_tf32f(v);
    }
    __syncthreads();

    int head = wid >> 1, chal = wid & 1;
    int tlo = (head*2    )*1536;
    int thi = (head*2 + 1)*1536;
    const float* Blo = Wa1 + ((size_t)head*3*HD + which*HD)*HD;
    const float* Bhi = Wa1 + ((size_t)head*3*HD + 2*HD)*HD;

    float acc[4][4];
#pragma unroll
    for (int nt = 0; nt < 4; ++nt)
        acc[nt][0]=acc[nt][1]=acc[nt][2]=acc[nt][3]=0.f;

#pragma unroll 4
    for (int ks = 0; ks < 8; ++ks) {
        int k0 = ks*8;
        uint32_t a0 = __float_as_uint(s1[tlo + (k0+tig)*24 + gid]);
        uint32_t a1 = __float_as_uint(s1[tlo + (k0+tig)*24 + gid + 8]);
        uint32_t a2 = __float_as_uint(s1[tlo + (k0+tig+4)*24 + gid]);
        uint32_t a3 = __float_as_uint(s1[tlo + (k0+tig+4)*24 + gid + 8]);
#pragma unroll
        for (int nt = 0; nt < 4; ++nt) {
            int col = chal*32 + nt*8 + gid;
            uint32_t b0 = cvt_tf32(Blo[(k0+tig)*HD + col]);
            uint32_t b1 = cvt_tf32(Blo[(k0+tig+4)*HD + col]);
            mma1688(acc[nt], a0, a1, a2, a3, b0, b1);
        }
    }
#pragma unroll 4
    for (int ks = 0; ks < 8; ++ks) {
        int k0 = ks*8;
        uint32_t a0 = __float_as_uint(s1[thi + (k0+tig)*24 + gid]);
        uint32_t a1 = __float_as_uint(s1[thi + (k0+tig)*24 + gid + 8]);
        uint32_t a2 = __float_as_uint(s1[thi + (k0+tig+4)*24 + gid]);
        uint32_t a3 = __float_as_uint(s1[thi + (k0+tig+4)*24 + gid + 8]);
#pragma unroll
        for (int nt = 0; nt < 4; ++nt) {
            int col = chal*32 + nt*8 + gid;
            uint32_t b0 = cvt_tf32(0.6f * Bhi[(k0+tig)*HD + col]);
            uint32_t b1 = cvt_tf32(0.6f * Bhi[(k0+tig+4)*HD + col]);
            mma1688(acc[nt], a0, a1, a2, a3, b0, b1);
        }
    }

    float* gout = which ? g_sj2 : g_si2;
#pragma unroll
    for (int nt = 0; nt < 4; ++nt) {
        int c0 = chal*32 + nt*8 + 2*tig;
        float v00=acc[nt][0], v01=acc[nt][1], v10=acc[nt][2], v11=acc[nt][3];
        if (which == 0) {
            float b0v = ba1[head*HD + c0], b1v = ba1[head*HD + c0 + 1];
            v00 += b0v; v01 += b1v; v10 += b0v; v11 += b1v;
        }
        size_t rbase = ((size_t)(b*NH + head)*NN + n0);
        *reinterpret_cast<float2*>(&gout[(rbase + gid)*HD + c0])     = make_float2(v00, v01);
        *reinterpret_cast<float2*>(&gout[(rbase + gid + 8)*HD + c0]) = make_float2(v10, v11);
    }
}

// ---------------------------------------------------------------------------
// t2f: exact R13/R15 (unchanged — protected).
// ---------------------------------------------------------------------------
#define O_EJ    0
#define O_WEBF  9216
#define O_EI    11264
#define O_SI    11776
#define O_WA2   12800
#define O_ET    12864
#define O_HP    17472
#define T2_FLOATS 18560
#define T2_BYTES  (T2_FLOATS*4)

__global__ __launch_bounds__(256, 2) void t2f(
    const float* __restrict__ Wa1, const float* __restrict__ wa2,
    const int*   __restrict__ adj, const float* __restrict__ ba2,
    const float* __restrict__ ln_g, const float* __restrict__ ln_b)
{
    extern __shared__ __align__(16) float sm[];
    uint32_t* smu = reinterpret_cast<uint32_t*>(sm);

    int bx   = blockIdx.x;
    int it   = bx & 15;
    int head = (bx >> 4) & 3;
    int b    = bx >> 6;
    int i0   = it * 16;
    int tid  = threadIdx.x;
    int wid  = tid >> 5, lane = tid & 31;
    int gid  = lane >> 2, tig = lane & 3;

    size_t bh = (size_t)(b*NH + head);
    const float* sj_base = g_sj2 + bh*NN*HD;
    const float* wh_base = g_Wh  + bh*NN*HD;

    for (int t = tid; t < NN*32; t += 256) {
        int j = t >> 5, kk = t & 31;
        float2 v = *reinterpret_cast<const float2*>(&g_ej[(bh*NN + j)*HD + 2*kk]);
        smu[O_EJ + j*36 + kk] = packbf(v.x, v.y);
    }
    for (int t = tid; t < 2048; t += 256) {
        int c   = t & 1;
        int ln2 = (t >> 1) & 31;
        int q   = t >> 6;
        int ks  = q >> 3, nt = q & 7;
        int tg  = ln2 & 3, gd = ln2 >> 2;
        int kk  = ks*8 + tg + (c ? 4 : 0);
        int d   = nt*8 + gd;
        float f0 = 0.4f * Wa1[((size_t)head*3*HD + 2*HD + 2*kk    )*HD + d];
        float f1 = 0.4f * Wa1[((size_t)head*3*HD + 2*HD + 2*kk + 1)*HD + d];
        smu[O_WEBF + t] = packbf(f0, f1);
    }
    for (int t = tid; t < 16*32; t += 256) {
        int ii = t >> 5, kk = t & 31;
        float2 v = *reinterpret_cast<const float2*>(&g_ei[(bh*NN + i0 + ii)*HD + 2*kk]);
        smu[O_EI + t] = packbf(v.x, v.y);
    }
    for (int t = tid; t < 16*64; t += 256) {
        int ii = t >> 6, d = t & 63;
        sm[O_SI + t] = g_si2[(bh*NN + i0 + ii)*HD + d];
    }
    if (tid < 64) sm[O_WA2 + tid] = wa2[head*HD + tid];
    __syncthreads();

    unsigned long long bfr[4][8];
#pragma unroll
    for (int ks = 0; ks < 4; ++ks)
#pragma unroll
        for (int nt = 0; nt < 8; ++nt)
            bfr[ks][nt] = *reinterpret_cast<const unsigned long long*>(
                &smu[O_WEBF + ((ks*8 + nt)*32 + lane)*2]);

    for (int ii = 0; ii < 16; ++ii) {
        uint32_t eir[8];
#pragma unroll
        for (int ks = 0; ks < 4; ++ks) {
            eir[2*ks]   = smu[O_EI + ii*32 + ks*8 + tig];
            eir[2*ks+1] = smu[O_EI + ii*32 + ks*8 + 4 + tig];
        }
#pragma unroll
        for (int p = 0; p < 2; ++p) {
            int j0 = (wid + 8*p) * 16;
            int r0 = j0 + gid, r1 = r0 + 8;

            float acc[8][4];
#pragma unroll
            for (int nt = 0; nt < 8; ++nt) {
                float2 s = *reinterpret_cast<const float2*>(&sm[O_SI + ii*64 + nt*8 + 2*tig]);
                acc[nt][0] = s.x; acc[nt][1] = s.y; acc[nt][2] = s.x; acc[nt][3] = s.y;
            }
#pragma unroll
            for (int ks = 0; ks < 4; ++ks) {
                uint32_t a0 = habs2(hadd2(smu[O_EJ + r0*36 + ks*8 + tig],     eir[2*ks]));
                uint32_t a1 = habs2(hadd2(smu[O_EJ + r1*36 + ks*8 + tig],     eir[2*ks]));
                uint32_t a2 = habs2(hadd2(smu[O_EJ + r0*36 + ks*8 + 4 + tig], eir[2*ks+1]));
                uint32_t a3 = habs2(hadd2(smu[O_EJ + r1*36 + ks*8 + 4 + tig], eir[2*ks+1]));
#pragma unroll
                for (int nt = 0; nt < 8; ++nt) {
                    uint32_t b0 = (uint32_t)(bfr[ks][nt] & 0xffffffffu);
                    uint32_t b1 = (uint32_t)(bfr[ks][nt] >> 32);
                    mma16816(acc[nt], a0, a1, a2, a3, b0, b1);
                }
            }
            float pe0 = 0.f, pe1 = 0.f;
#pragma unroll
            for (int nt = 0; nt < 8; ++nt) {
                int d = nt*8 + 2*tig;
                float2 sj0 = *reinterpret_cast<const float2*>(&sj_base[(size_t)r0*HD + d]);
                float2 sj1 = *reinterpret_cast<const float2*>(&sj_base[(size_t)r1*HD + d]);
                float2 w2  = *reinterpret_cast<const float2*>(&sm[O_WA2 + d]);
                float v00 = acc[nt][0] + sj0.x, v01 = acc[nt][1] + sj0.y;
                float v10 = acc[nt][2] + sj1.x, v11 = acc[nt][3] + sj1.y;
                pe0 = fmaf(fmaxf(v00, ALPHA*v00), w2.x, pe0);
                pe0 = fmaf(fmaxf(v01, ALPHA*v01), w2.y, pe0);
                pe1 = fmaf(fmaxf(v10, ALPHA*v10), w2.x, pe1);
                pe1 = fmaf(fmaxf(v11, ALPHA*v11), w2.y, pe1);
            }
            pe0 += __shfl_xor_sync(0xffffffffu, pe0, 1);
            pe0 += __shfl_xor_sync(0xffffffffu, pe0, 2);
            pe1 += __shfl_xor_sync(0xffffffffu, pe1, 1);
            pe1 += __shfl_xor_sync(0xffffffffu, pe1, 2);
            if (tig == 0) {
                sm[O_ET + r0*18 + ii] = pe0;
                sm[O_ET + r1*18 + ii] = pe1;
            }
        }
    }
    __syncthreads();

    {
        float bav = ba2[head];
#pragma unroll
        for (int r = 0; r < 2; ++r) {
            int i = wid*2 + r;
            int iglob = i0 + i;
            float vals[8]; float mx = -1e30f;
#pragma unroll
            for (int s = 0; s < 8; ++s) {
                int j = lane + 32*s;
                float pe = sm[O_ET + j*18 + i] + bav;
                int a = adj[((size_t)b*NN + iglob)*NN + j];
                vals[s] = (a == 0) ? -1e9f : pe;
                mx = fmaxf(mx, vals[s]);
            }
#pragma unroll
            for (int o = 16; o; o >>= 1) mx = fmaxf(mx, __shfl_xor_sync(0xffffffffu, mx, o));
            float se = 0.f;
#pragma unroll
            for (int s = 0; s < 8; ++s) { vals[s] = __expf(vals[s] - mx); se += vals[s]; }
#pragma unroll
            for (int o = 16; o; o >>= 1) se += __shfl_xor_sync(0xffffffffu, se, o);
            float inv = 1.0f / se;
#pragma unroll
            for (int s = 0; s < 8; ++s)
                sm[O_ET + (lane + 32*s)*18 + i] = vals[s] * inv;
        }
    }
    __syncthreads();

    {
        int n0w = wid * 8;
        float hacc[4] = {0.f, 0.f, 0.f, 0.f};
#pragma unroll 4
        for (int ks = 0; ks < 32; ++ks) {
            int k0 = ks*8;
            uint32_t a0 = cvt_tf32(sm[O_ET + (k0+tig)*18 + gid]);
            uint32_t a1 = cvt_tf32(sm[O_ET + (k0+tig)*18 + gid + 8]);
            uint32_t a2 = cvt_tf32(sm[O_ET + (k0+tig+4)*18 + gid]);
            uint32_t a3 = cvt_tf32(sm[O_ET + (k0+tig+4)*18 + gid + 8]);
            uint32_t b0 = cvt_tf32(wh_base[(size_t)(k0+tig)*HD + n0w + gid]);
            uint32_t b1 = cvt_tf32(wh_base[(size_t)(k0+tig+4)*HD + n0w + gid]);
            mma1688(hacc, a0, a1, a2, a3, b0, b1);
        }
        int c0 = n0w + 2*tig;
        sm[O_HP + gid*68 + c0]         = hacc[0];
        sm[O_HP + gid*68 + c0 + 1]     = hacc[1];
        sm[O_HP + (gid+8)*68 + c0]     = hacc[2];
        sm[O_HP + (gid+8)*68 + c0 + 1] = hacc[3];
    }
    __syncthreads();

    {
#pragma unroll
        for (int r = 0; r < 2; ++r) {
            int i = wid*2 + r;
            float x0 = sm[O_HP + i*68 + lane];
            float x1 = sm[O_HP + i*68 + 32 + lane];
            float s1v = x0 + x1, s2v = x0*x0 + x1*x1;
#pragma unroll
            for (int o = 16; o; o >>= 1) {
                s1v += __shfl_xor_sync(0xffffffffu, s1v, o);
                s2v += __shfl_xor_sync(0xffffffffu, s2v, o);
            }
            float m   = s1v * (1.0f/64.0f);
            float var = s2v * (1.0f/64.0f) - m*m;
            float rr  = rsqrtf(var + 1e-5f);
            size_t obase = ((size_t)(b*NN) + i0 + i)*FIN + head*HD;
            g_concat[obase + lane]      = (x0 - m)*rr*ln_g[head*HD + lane]      + ln_b[head*HD + lane];
            g_concat[obase + 32 + lane] = (x1 - m)*rr*ln_g[head*HD + 32 + lane] + ln_b[head*HD + 32 + lane];
        }
    }
}

// ---------------------------------------------------------------------------
// Kernel 3 (tf32 MMA, R13/R15 single-kernel version; k-loop unroll 8).
// ---------------------------------------------------------------------------
__global__ __launch_bounds__(256) void k3_out(
    const float* __restrict__ hin, const float* __restrict__ Wo,
    const float* __restrict__ bo,  const float* __restrict__ g2,
    const float* __restrict__ b2,  float* __restrict__ out)
{
    __shared__ __align__(16) float cst[FIN*24];
    __shared__ float obuf[16][260];
    int b  = blockIdx.x >> 4;
    int n0 = (blockIdx.x & 15) * 16;
    int tid = threadIdx.x;
    int wid = tid >> 5, lane = tid & 31;
    int gid = lane >> 2, tig = lane & 3;

    {
        const float* crow = g_concat + ((size_t)b*NN + n0)*FIN + tid;
#pragma unroll
        for (int r = 0; r < 16; ++r)
            cst[tid*24 + r] = cvt_tf32f(crow[(size_t)r*FIN]);
    }
    __syncthreads();

    float acc[4][4];
#pragma unroll
    for (int nt = 0; nt < 4; ++nt)
        acc[nt][0]=acc[nt][1]=acc[nt][2]=acc[nt][3]=0.f;

#pragma unroll 8
    for (int k0 = 0; k0 < FIN; k0 += 8) {
        uint32_t a0 = __float_as_uint(cst[(k0+tig)*24 + gid]);
        uint32_t a1 = __float_as_uint(cst[(k0+tig)*24 + gid + 8]);
        uint32_t a2 = __float_as_uint(cst[(k0+tig+4)*24 + gid]);
        uint32_t a3 = __float_as_uint(cst[(k0+tig+4)*24 + gid + 8]);
#pragma unroll
        for (int nt = 0; nt < 4; ++nt) {
            int col = wid*32 + nt*8 + gid;
            uint32_t b0 = cvt_tf32(Wo[(size_t)(k0+tig)*FIN + col]);
            uint32_t b1 = cvt_tf32(Wo[(size_t)(k0+tig+4)*FIN + col]);
            mma1688(acc[nt], a0, a1, a2, a3, b0, b1);
        }
    }

#pragma unroll
    for (int nt = 0; nt < 4; ++nt) {
        int c0 = wid*32 + nt*8 + 2*tig;
        float b0v = bo[c0], b1v = bo[c0+1];
        float2 h0 = *reinterpret_cast<const float2*>(&hin[((size_t)b*NN + n0 + gid)*FIN + c0]);
        float2 h1 = *reinterpret_cast<const float2*>(&hin[((size_t)b*NN + n0 + gid + 8)*FIN + c0]);
        obuf[gid][c0]       = acc[nt][0] + b0v + h0.x;
        obuf[gid][c0+1]     = acc[nt][1] + b1v + h0.y;
        obuf[gid+8][c0]     = acc[nt][2] + b0v + h1.x;
        obuf[gid+8][c0+1]   = acc[nt][3] + b1v + h1.y;
    }
    __syncthreads();

#pragma unroll
    for (int r = 0; r < 2; ++r) {
        int row = wid*2 + r;
        float s1v = 0.f, s2v = 0.f;
#pragma unroll
        for (int k = 0; k < 8; ++k) {
            float x = obuf[row][k*32 + lane];
            s1v += x; s2v += x*x;
        }
#pragma unroll
        for (int o = 16; o; o >>= 1) {
            s1v += __shfl_xor_sync(0xffffffffu, s1v, o);
            s2v += __shfl_xor_sync(0xffffffffu, s2v, o);
        }
        float m   = s1v * (1.0f/256.0f);
        float var = s2v * (1.0f/256.0f) - m*m;
        float rr  = rsqrtf(var + 1e-5f);
#pragma unroll
        for (int k = 0; k < 8; ++k) {
            int c = k*32 + lane;
            float x = obuf[row][c];
            out[((size_t)b*NN + n0 + row)*FIN + c] = (x - m)*rr*g2[c] + b2[c];
        }
    }
}

// ---------------------------------------------------------------------------
extern "C" void kernel_launch(void* const* d_in, const int* in_sizes, int n_in,
                              void* d_out, int out_size)
{
    const float* h    = (const float*)d_in[0];
    const int*   adj  = (const int*)  d_in[1];
    const float* W    = (const float*)d_in[2];
    const float* We1  = (const float*)d_in[3];
    const float* be1  = (const float*)d_in[4];
    const float* Wa1  = (const float*)d_in[5];
    const float* ba1  = (const float*)d_in[6];
    const float* wa2  = (const float*)d_in[7];
    const float* ba2  = (const float*)d_in[8];
    const float* ln_g = (const float*)d_in[9];
    const float* ln_b = (const float*)d_in[10];
    const float* Wo   = (const float*)d_in[11];
    const float* bo   = (const float*)d_in[12];
    const float* g2   = (const float*)d_in[13];
    const float* b2   = (const float*)d_in[14];
    float* out = (float*)d_out;

    cudaFuncSetAttribute(k1a,  cudaFuncAttributeMaxDynamicSharedMemorySize, K1A_BYTES);
    cudaFuncSetAttribute(k1b2, cudaFuncAttributeMaxDynamicSharedMemorySize, K1B_BYTES);
    cudaFuncSetAttribute(t2f,  cudaFuncAttributeMaxDynamicSharedMemorySize, T2_BYTES);

    k1a    <<<NB*16*2, 256, K1A_BYTES>>>(h, W, We1, be1);
    k1b2   <<<NB*16*2, 256, K1B_BYTES>>>(Wa1, ba1);
    t2f    <<<NB*NH*(NN/16), 256, T2_BYTES>>>(Wa1, wa2, adj, ba2, ln_g, ln_b);
    k3_out <<<NB*(NN/16), 256>>>(h, Wo, bo, g2, b2, out);
}